// round 16
// baseline (speedup 1.0000x reference)
#include <cuda_runtime.h>
#include <cuda_bf16.h>
#include <cuda_fp16.h>
#include <cstdint>

namespace {

constexpr int BATCH = 4;
constexpr int SEQ   = 2048;
constexpr int FDIM  = 1024;
constexpr int NTOT  = BATCH * SEQ;   // 8192

constexpr int NTHR = 128;

// ---- shared geometry: 64x128 CTA tile, BK=32 (64B rows, 80B padded), occ 3
constexpr int BM = 64, BN = 128, BK = 32;
constexpr int R3_ROW     = 80;                   // 64B data + 16B pad (conflict-free)
constexpr int A_OP_BYTES = 64  * R3_ROW;         // 5120
constexpr int B_OP_BYTES = 128 * R3_ROW;         // 10240
constexpr int STAGE_BYTES = 2 * A_OP_BYTES + 2 * B_OP_BYTES;   // 30720 (3-term)
constexpr int SMEM_BYTES  = 2 * STAGE_BYTES;     // 61440

// ---- PV (1-term): same CTA/warp geometry, hi-only operands
constexpr int P_STAGE = A_OP_BYTES + B_OP_BYTES; // 15360... A is 64 rows, B 128 rows
// NOTE: A tile = 64x32 fp16 (80B rows) = 5120 B; B tile = 128x32 = 10240 B.
constexpr int P_SMEM  = 2 * P_STAGE;             // 30720 -> 3 CTAs/SM easily

// ---------------- device scratch ----------------
__device__ __nv_bfloat16 g_xh[(size_t)NTOT * FDIM];
__device__ __nv_bfloat16 g_xl[(size_t)NTOT * FDIM];
__device__ __nv_bfloat16 g_wh[(size_t)3 * FDIM * FDIM];
__device__ __nv_bfloat16 g_wl[(size_t)3 * FDIM * FDIM];
__device__ __nv_bfloat16 g_qh[(size_t)NTOT * FDIM];
__device__ __nv_bfloat16 g_ql[(size_t)NTOT * FDIM];
__device__ __nv_bfloat16 g_kh[(size_t)NTOT * FDIM];
__device__ __nv_bfloat16 g_kl[(size_t)NTOT * FDIM];
__device__ __half        g_vth[(size_t)NTOT * FDIM];  // v^T [b][o][s], fp16 hi only
__device__ float         g_logits[(size_t)BATCH * SEQ * SEQ];
__device__ __half        g_ph[(size_t)BATCH * SEQ * SEQ];   // P fp16 (single)

// ---------------- helpers ----------------
__device__ __forceinline__ uint32_t smem_u32(const void* p) {
    uint32_t a;
    asm("{ .reg .u64 t; cvta.to.shared.u64 t, %1; cvt.u32.u64 %0, t; }"
        : "=r"(a) : "l"(p));
    return a;
}
__device__ __forceinline__ void cp16(uint32_t saddr, const void* gaddr) {
    asm volatile("cp.async.cg.shared.global [%0], [%1], 16;"
                 :: "r"(saddr), "l"(gaddr) : "memory");
}
__device__ __forceinline__ void cp_commit() {
    asm volatile("cp.async.commit_group;" ::: "memory");
}
template<int N>
__device__ __forceinline__ void cp_wait() {
    asm volatile("cp.async.wait_group %0;" :: "n"(N) : "memory");
}

#define LDSM_X4(R, addr) \
    asm volatile("ldmatrix.sync.aligned.m8n8.x4.shared.b16 {%0,%1,%2,%3}, [%4];" \
                 : "=r"((R)[0]), "=r"((R)[1]), "=r"((R)[2]), "=r"((R)[3]) \
                 : "r"(addr))

__device__ __forceinline__ void mma_bf16(float* d, const uint32_t* a,
                                         uint32_t b0, uint32_t b1) {
    asm volatile("mma.sync.aligned.m16n8k16.row.col.f32.bf16.bf16.f32 "
                 "{%0,%1,%2,%3}, {%4,%5,%6,%7}, {%8,%9}, {%0,%1,%2,%3};"
                 : "+f"(d[0]), "+f"(d[1]), "+f"(d[2]), "+f"(d[3])
                 : "r"(a[0]), "r"(a[1]), "r"(a[2]), "r"(a[3]), "r"(b0), "r"(b1));
}
__device__ __forceinline__ void mma_f16(float* d, const uint32_t* a,
                                        uint32_t b0, uint32_t b1) {
    asm volatile("mma.sync.aligned.m16n8k16.row.col.f32.f16.f16.f32 "
                 "{%0,%1,%2,%3}, {%4,%5,%6,%7}, {%8,%9}, {%0,%1,%2,%3};"
                 : "+f"(d[0]), "+f"(d[1]), "+f"(d[2]), "+f"(d[3])
                 : "r"(a[0]), "r"(a[1]), "r"(a[2]), "r"(a[3]), "r"(b0), "r"(b1));
}

__device__ __forceinline__ void split2(float v, __nv_bfloat16& h, __nv_bfloat16& l) {
    h = __float2bfloat16(v);
    l = __float2bfloat16(v - __bfloat162float(h));
}

// ============================================================================
// 3-term mainloop: 4 warps = 2(M) x 2(N); warp tile 32x64; acc[2][8][4].
// AhBh + AhBl + AlBh, fp32 acc. BK=32 (2 k16 steps/chunk), 80B rows.
// ============================================================================
__device__ __forceinline__ void run_mainloop3(
    const uint16_t* __restrict__ Ah, const uint16_t* __restrict__ Al,
    const uint16_t* __restrict__ Bh, const uint16_t* __restrict__ Bl,
    int ldA, int ldB, int K, uint32_t smem_u, int tid,
    float acc[2][8][4])
{
    const int wid = tid >> 5, lid = tid & 31;
    const int warp_m = wid & 1, warp_n = wid >> 1;   // 2 x 2
    const int q = lid >> 3, lr = lid & 7;
    const int rowA = (q & 1) * 8 + lr, kA8 = (q >> 1) * 8;
    const int rowB = (q >> 1) * 8 + lr, kB8 = (q & 1) * 8;

    auto issue = [&](int c) {
        const int k0 = c * BK;
        const uint32_t st = smem_u + (c & 1) * STAGE_BYTES;
#pragma unroll
        for (int op = 0; op < 2; op++) {
            const uint16_t* s = op ? Al : Ah;
#pragma unroll
            for (int i = 0; i < 2; i++) {
                int seg = i * NTHR + tid;
                int r = seg >> 2, cs = seg & 3;
                cp16(st + op * A_OP_BYTES + r * R3_ROW + cs * 16,
                     s + (size_t)r * ldA + k0 + cs * 8);
            }
        }
#pragma unroll
        for (int op = 0; op < 2; op++) {
            const uint16_t* s = op ? Bl : Bh;
#pragma unroll
            for (int i = 0; i < 4; i++) {
                int seg = i * NTHR + tid;
                int r = seg >> 2, cs = seg & 3;
                cp16(st + 2 * A_OP_BYTES + op * B_OP_BYTES + r * R3_ROW + cs * 16,
                     s + (size_t)r * ldB + k0 + cs * 8);
            }
        }
        cp_commit();
    };

    const int NC = K / BK;
    issue(0);

    for (int c = 0; c < NC; c++) {
        if (c + 1 < NC) { issue(c + 1); cp_wait<1>(); }
        else            { cp_wait<0>(); }
        __syncthreads();

        const uint32_t st = smem_u + (c & 1) * STAGE_BYTES;
        const uint32_t aH = st + (warp_m * 32 + rowA) * R3_ROW + kA8 * 2;
        const uint32_t aL = aH + A_OP_BYTES;
        const uint32_t bH = st + 2 * A_OP_BYTES
                          + (warp_n * 64 + rowB) * R3_ROW + kB8 * 2;
        const uint32_t bL = bH + B_OP_BYTES;

#pragma unroll
        for (int ks = 0; ks < 2; ks++) {
            const int kb = ks * 32;
            uint32_t ah[2][4], al[2][4], bh[4][4], bl[4][4];
#pragma unroll
            for (int t = 0; t < 2; t++) {
                LDSM_X4(ah[t], aH + t * 16 * R3_ROW + kb);
                LDSM_X4(al[t], aL + t * 16 * R3_ROW + kb);
            }
#pragma unroll
            for (int p = 0; p < 4; p++) {
                LDSM_X4(bh[p], bH + p * 16 * R3_ROW + kb);
                LDSM_X4(bl[p], bL + p * 16 * R3_ROW + kb);
            }
#pragma unroll
            for (int t = 0; t < 2; t++) {
#pragma unroll
                for (int p = 0; p < 4; p++) {
#pragma unroll
                    for (int h = 0; h < 2; h++) {
                        float* d = acc[t][2 * p + h];
                        mma_bf16(d, ah[t], bh[p][2 * h], bh[p][2 * h + 1]);
                        mma_bf16(d, ah[t], bl[p][2 * h], bl[p][2 * h + 1]);
                        mma_bf16(d, al[t], bh[p][2 * h], bh[p][2 * h + 1]);
                    }
                }
            }
        }
        __syncthreads();
    }
}

// ============================================================================
// QK^T GEMM (bf16 3-term, fp32 epilogue)
// ============================================================================
__global__ __launch_bounds__(NTHR, 3)
void gemm_qk(const uint16_t* __restrict__ Ah, const uint16_t* __restrict__ Al,
             long sA, int ldA,
             const uint16_t* __restrict__ Bh, const uint16_t* __restrict__ Bl,
             long sB, int ldB,
             float* __restrict__ dst, long sC, int ldC, int K)
{
    extern __shared__ char smem[];
    const uint32_t smem_u = smem_u32(smem);
    const int tid = threadIdx.x;
    const int wid = tid >> 5, lid = tid & 31;
    const int warp_m = wid & 1, warp_n = wid >> 1;
    const int m0 = blockIdx.y * BM, n0 = blockIdx.x * BN;

    const uint16_t* ah = Ah + (long)blockIdx.z * sA + (size_t)m0 * ldA;
    const uint16_t* al = Al + (long)blockIdx.z * sA + (size_t)m0 * ldA;
    const uint16_t* bh = Bh + (long)blockIdx.z * sB + (size_t)n0 * ldB;
    const uint16_t* bl = Bl + (long)blockIdx.z * sB + (size_t)n0 * ldB;

    float acc[2][8][4];
#pragma unroll
    for (int t = 0; t < 2; t++)
#pragma unroll
        for (int n = 0; n < 8; n++)
#pragma unroll
            for (int e = 0; e < 4; e++) acc[t][n][e] = 0.0f;

    run_mainloop3(ah, al, bh, bl, ldA, ldB, K, smem_u, tid, acc);

    const int tq = lid >> 2, tr2 = (lid & 3) * 2;
    float* base = dst + (long)blockIdx.z * sC;
#pragma unroll
    for (int t = 0; t < 2; t++) {
        long m = m0 + warp_m * 32 + t * 16 + tq;
#pragma unroll
        for (int j = 0; j < 8; j++) {
            int n = n0 + warp_n * 64 + j * 8 + tr2;
            *reinterpret_cast<float2*>(base + m * ldC + n) =
                make_float2(acc[t][j][0], acc[t][j][1]);
            *reinterpret_cast<float2*>(base + (m + 8) * ldC + n) =
                make_float2(acc[t][j][2], acc[t][j][3]);
        }
    }
}

// ============================================================================
// PV GEMM: fp16 1-term, CTA 64x128, 4 warps of 32x64, BK=32, occ 3.
// out[m,n] = sum_k P[m,k] * Vt[n,k]
// ============================================================================
__global__ __launch_bounds__(NTHR, 3)
void pv_gemm(const uint16_t* __restrict__ P, long sP,
             const uint16_t* __restrict__ Vt, long sV,
             float* __restrict__ dst, long sC)
{
    extern __shared__ char smem[];
    const uint32_t smem_u = smem_u32(smem);
    const int tid = threadIdx.x;
    const int wid = tid >> 5, lid = tid & 31;
    const int warp_m = wid & 1, warp_n = wid >> 1;   // 2 x 2 of 32x64
    const int m0 = blockIdx.y * BM, n0 = blockIdx.x * BN;
    const int ldA = SEQ, ldB = SEQ, K = SEQ;

    const uint16_t* ah = P  + (long)blockIdx.z * sP + (size_t)m0 * ldA;
    const uint16_t* bh = Vt + (long)blockIdx.z * sV + (size_t)n0 * ldB;

    const int q = lid >> 3, lr = lid & 7;
    const int rowA = (q & 1) * 8 + lr, kA8 = (q >> 1) * 8;
    const int rowB = (q >> 1) * 8 + lr, kB8 = (q & 1) * 8;

    float acc[2][8][4];
#pragma unroll
    for (int t = 0; t < 2; t++)
#pragma unroll
        for (int n = 0; n < 8; n++)
#pragma unroll
            for (int e = 0; e < 4; e++) acc[t][n][e] = 0.0f;

    auto issue = [&](int c) {
        const int k0 = c * BK;
        const uint32_t st = smem_u + (c & 1) * P_STAGE;
        // A: 64 rows x 4 segs = 256 segs -> 2 iters of 128 thr
#pragma unroll
        for (int i = 0; i < 2; i++) {
            int seg = i * NTHR + tid;
            int r = seg >> 2, cs = seg & 3;
            cp16(st + r * R3_ROW + cs * 16, ah + (size_t)r * ldA + k0 + cs * 8);
        }
        // B: 128 rows x 4 segs = 512 segs -> 4 iters
#pragma unroll
        for (int i = 0; i < 4; i++) {
            int seg = i * NTHR + tid;
            int r = seg >> 2, cs = seg & 3;
            cp16(st + A_OP_BYTES + r * R3_ROW + cs * 16,
                 bh + (size_t)r * ldB + k0 + cs * 8);
        }
        cp_commit();
    };

    const int NC = K / BK;
    issue(0);

    for (int c = 0; c < NC; c++) {
        if (c + 1 < NC) { issue(c + 1); cp_wait<1>(); }
        else            { cp_wait<0>(); }
        __syncthreads();

        const uint32_t st = smem_u + (c & 1) * P_STAGE;
        const uint32_t aH = st + (warp_m * 32 + rowA) * R3_ROW + kA8 * 2;
        const uint32_t bH = st + A_OP_BYTES
                          + (warp_n * 64 + rowB) * R3_ROW + kB8 * 2;

#pragma unroll
        for (int ks = 0; ks < 2; ks++) {
            const int kb = ks * 32;
            uint32_t af[2][4], bf[4][4];
#pragma unroll
            for (int t = 0; t < 2; t++)
                LDSM_X4(af[t], aH + t * 16 * R3_ROW + kb);
#pragma unroll
            for (int p = 0; p < 4; p++)
                LDSM_X4(bf[p], bH + p * 16 * R3_ROW + kb);
#pragma unroll
            for (int t = 0; t < 2; t++) {
#pragma unroll
                for (int p = 0; p < 4; p++) {
#pragma unroll
                    for (int h = 0; h < 2; h++)
                        mma_f16(acc[t][2 * p + h], af[t],
                                bf[p][2 * h], bf[p][2 * h + 1]);
                }
            }
        }
        __syncthreads();
    }

    const int tq = lid >> 2, tr2 = (lid & 3) * 2;
    float* base = dst + (long)blockIdx.z * sC;
#pragma unroll
    for (int t = 0; t < 2; t++) {
        long m = m0 + warp_m * 32 + t * 16 + tq;
#pragma unroll
        for (int j = 0; j < 8; j++) {
            int n = n0 + warp_n * 64 + j * 8 + tr2;
            *reinterpret_cast<float2*>(base + m * FDIM + n) =
                make_float2(acc[t][j][0], acc[t][j][1]);
            *reinterpret_cast<float2*>(base + (m + 8) * FDIM + n) =
                make_float2(acc[t][j][2], acc[t][j][3]);
        }
    }
}

// ============================================================================
// Fused projection kernel: z=0 -> q (bf16 hi/lo), z=1 -> k (bf16 hi/lo),
// z=2 -> v transposed (fp16 hi only). relu(x W^T + b). bf16 3-term mainloop.
// ============================================================================
__global__ __launch_bounds__(NTHR, 3)
void proj_kernel(const __nv_bfloat16* __restrict__ xh, const __nv_bfloat16* __restrict__ xl,
                 const __nv_bfloat16* __restrict__ wh, const __nv_bfloat16* __restrict__ wl,
                 const float* __restrict__ bq, const float* __restrict__ bk,
                 const float* __restrict__ bv,
                 __nv_bfloat16* __restrict__ qh, __nv_bfloat16* __restrict__ ql,
                 __nv_bfloat16* __restrict__ kh, __nv_bfloat16* __restrict__ kl,
                 __half* __restrict__ vth)
{
    extern __shared__ char smem[];
    const uint32_t smem_u = smem_u32(smem);
    const int tid = threadIdx.x;
    const int wid = tid >> 5, lid = tid & 31;
    const int warp_m = wid & 1, warp_n = wid >> 1;
    const int m0 = blockIdx.y * BM, n0 = blockIdx.x * BN;
    const int z = blockIdx.z;
    const long WSZ = (long)FDIM * FDIM;

    const float* bias = (z == 0) ? bq : (z == 1) ? bk : bv;
    const uint16_t* ah = (const uint16_t*)xh + (size_t)m0 * FDIM;
    const uint16_t* al = (const uint16_t*)xl + (size_t)m0 * FDIM;
    const uint16_t* bhp = (const uint16_t*)wh + z * WSZ + (size_t)n0 * FDIM;
    const uint16_t* blp = (const uint16_t*)wl + z * WSZ + (size_t)n0 * FDIM;

    float acc[2][8][4];
#pragma unroll
    for (int t = 0; t < 2; t++)
#pragma unroll
        for (int n = 0; n < 8; n++)
#pragma unroll
            for (int e = 0; e < 4; e++) acc[t][n][e] = 0.0f;

    run_mainloop3(ah, al, bhp, blp, FDIM, FDIM, FDIM, smem_u, tid, acc);

    const int tq = lid >> 2, tr2 = (lid & 3) * 2;

    if (z < 2) {
        __nv_bfloat16* dh = (z == 0) ? qh : kh;
        __nv_bfloat16* dl = (z == 0) ? ql : kl;
#pragma unroll
        for (int t = 0; t < 2; t++) {
            long m = m0 + warp_m * 32 + t * 16 + tq;
#pragma unroll
            for (int j = 0; j < 8; j++) {
                int n = n0 + warp_n * 64 + j * 8 + tr2;
                float b0 = bias[n], b1 = bias[n + 1];
#pragma unroll
                for (int h = 0; h < 2; h++) {
                    float v0 = fmaxf(acc[t][j][2 * h + 0] + b0, 0.0f);
                    float v1 = fmaxf(acc[t][j][2 * h + 1] + b1, 0.0f);
                    __nv_bfloat16 h0, l0, h1, l1;
                    split2(v0, h0, l0); split2(v1, h1, l1);
                    long row = m + 8 * h;
                    *reinterpret_cast<__nv_bfloat162*>(dh + row * FDIM + n) =
                        __nv_bfloat162(h0, h1);
                    *reinterpret_cast<__nv_bfloat162*>(dl + row * FDIM + n) =
                        __nv_bfloat162(l0, l1);
                }
            }
        }
    } else {
        // v: relu+bias, stage fp32 in smem [64][129], write transposed fp16
        float* smf = (float*)smem;
#pragma unroll
        for (int t = 0; t < 2; t++) {
            int ml = warp_m * 32 + t * 16 + tq;
#pragma unroll
            for (int j = 0; j < 8; j++) {
                int nl = warp_n * 64 + j * 8 + tr2;
                float b0 = bias[n0 + nl], b1 = bias[n0 + nl + 1];
                smf[ml * 129 + nl]           = fmaxf(acc[t][j][0] + b0, 0.0f);
                smf[ml * 129 + nl + 1]       = fmaxf(acc[t][j][1] + b1, 0.0f);
                smf[(ml + 8) * 129 + nl]     = fmaxf(acc[t][j][2] + b0, 0.0f);
                smf[(ml + 8) * 129 + nl + 1] = fmaxf(acc[t][j][3] + b1, 0.0f);
            }
        }
        __syncthreads();
        const int o_l = tid;                 // 0..127 output feature
        const long bidx = m0 >> 11;
        const long s_g  = (m0 & 2047);
        __half* dh = vth + bidx * (long)FDIM * SEQ
                     + (long)(n0 + o_l) * SEQ + s_g;
#pragma unroll
        for (int g = 0; g < 64; g += 8) {
            __align__(16) __half hb[8];
#pragma unroll
            for (int j = 0; j < 8; j++)
                hb[j] = __float2half(smf[(g + j) * 129 + o_l]);
            *reinterpret_cast<uint4*>(dh + g) = *reinterpret_cast<const uint4*>(hb);
        }
    }
}

// ---------------- fused split: x, Wq, Wk, Wv -> bf16 hi/lo ----------------
__global__ __launch_bounds__(256)
void split_all(const float* __restrict__ x,
               const float* __restrict__ wq, const float* __restrict__ wk,
               const float* __restrict__ wv,
               __nv_bfloat16* __restrict__ xh, __nv_bfloat16* __restrict__ xl,
               __nv_bfloat16* __restrict__ wh, __nv_bfloat16* __restrict__ wl,
               int n4x, int n4w)
{
    int i = blockIdx.x * blockDim.x + threadIdx.x;
    const float* src; __nv_bfloat16 *dh, *dl; int idx;
    if (i < n4x)                { src = x;  dh = xh; dl = xl; idx = i; }
    else if (i < n4x + n4w)     { src = wq; dh = wh; dl = wl; idx = i - n4x; }
    else if (i < n4x + 2*n4w)   { src = wk; dh = wh + (long)FDIM*FDIM;
                                  dl = wl + (long)FDIM*FDIM; idx = i - n4x - n4w; }
    else if (i < n4x + 3*n4w)   { src = wv; dh = wh + 2L*FDIM*FDIM;
                                  dl = wl + 2L*FDIM*FDIM; idx = i - n4x - 2*n4w; }
    else return;

    float4 v = reinterpret_cast<const float4*>(src)[idx];
    __align__(8) __nv_bfloat16 hb[4], lb[4];
    split2(v.x, hb[0], lb[0]); split2(v.y, hb[1], lb[1]);
    split2(v.z, hb[2], lb[2]); split2(v.w, hb[3], lb[3]);
    reinterpret_cast<uint2*>(dh)[idx] = *reinterpret_cast<const uint2*>(hb);
    reinterpret_cast<uint2*>(dl)[idx] = *reinterpret_cast<const uint2*>(lb);
}

// ---------------- softmax row 2048, fp16 output (single) ----------------
__global__ __launch_bounds__(256)
void softmax_f16(const float* __restrict__ L, __half* __restrict__ ph)
{
    const int tid = threadIdx.x;
    const float* row = L + (size_t)blockIdx.x * SEQ;

    float4 v0 = reinterpret_cast<const float4*>(row)[tid];
    float4 v1 = reinterpret_cast<const float4*>(row)[tid + 256];

    float mx = fmaxf(fmaxf(fmaxf(v0.x, v0.y), fmaxf(v0.z, v0.w)),
                     fmaxf(fmaxf(v1.x, v1.y), fmaxf(v1.z, v1.w)));
    __shared__ float red[256];
    red[tid] = mx; __syncthreads();
#pragma unroll
    for (int s = 128; s > 0; s >>= 1) {
        if (tid < s) red[tid] = fmaxf(red[tid], red[tid + s]);
        __syncthreads();
    }
    mx = red[0]; __syncthreads();

    float e0x = __expf(v0.x - mx), e0y = __expf(v0.y - mx);
    float e0z = __expf(v0.z - mx), e0w = __expf(v0.w - mx);
    float e1x = __expf(v1.x - mx), e1y = __expf(v1.y - mx);
    float e1z = __expf(v1.z - mx), e1w = __expf(v1.w - mx);

    float sum = (e0x + e0y + e0z + e0w) + (e1x + e1y + e1z + e1w);
    red[tid] = sum; __syncthreads();
#pragma unroll
    for (int s = 128; s > 0; s >>= 1) {
        if (tid < s) red[tid] += red[tid + s];
        __syncthreads();
    }
    float inv = 1.0f / red[0];

    __half* ph_row = ph + (size_t)blockIdx.x * SEQ;
    __align__(8) __half hb[4];

    hb[0] = __float2half(e0x * inv); hb[1] = __float2half(e0y * inv);
    hb[2] = __float2half(e0z * inv); hb[3] = __float2half(e0w * inv);
    reinterpret_cast<uint2*>(ph_row)[tid] = *reinterpret_cast<const uint2*>(hb);

    hb[0] = __float2half(e1x * inv); hb[1] = __float2half(e1y * inv);
    hb[2] = __float2half(e1z * inv); hb[3] = __float2half(e1w * inv);
    reinterpret_cast<uint2*>(ph_row)[tid + 256] = *reinterpret_cast<const uint2*>(hb);
}

} // namespace

extern "C" void kernel_launch(void* const* d_in, const int* in_sizes, int n_in,
                              void* d_out, int out_size)
{
    const float* x  = (const float*)d_in[0];
    const float* Wq = (const float*)d_in[1];
    const float* bq = (const float*)d_in[2];
    const float* Wk = (const float*)d_in[3];
    const float* bk = (const float*)d_in[4];
    const float* Wv = (const float*)d_in[5];
    const float* bv = (const float*)d_in[6];
    float* out = (float*)d_out;

    __nv_bfloat16 *xh, *xl, *wh, *wl, *qh, *ql, *kh, *kl;
    __half *vth, *ph;
    float* logits;
    cudaGetSymbolAddress((void**)&xh, g_xh);   cudaGetSymbolAddress((void**)&xl, g_xl);
    cudaGetSymbolAddress((void**)&wh, g_wh);   cudaGetSymbolAddress((void**)&wl, g_wl);
    cudaGetSymbolAddress((void**)&qh, g_qh);   cudaGetSymbolAddress((void**)&ql, g_ql);
    cudaGetSymbolAddress((void**)&kh, g_kh);   cudaGetSymbolAddress((void**)&kl, g_kl);
    cudaGetSymbolAddress((void**)&vth, g_vth);
    cudaGetSymbolAddress((void**)&ph, g_ph);
    cudaGetSymbolAddress((void**)&logits, g_logits);

    cudaFuncSetAttribute(proj_kernel,
                         cudaFuncAttributeMaxDynamicSharedMemorySize, SMEM_BYTES);
    cudaFuncSetAttribute(gemm_qk,
                         cudaFuncAttributeMaxDynamicSharedMemorySize, SMEM_BYTES);
    cudaFuncSetAttribute(pv_gemm,
                         cudaFuncAttributeMaxDynamicSharedMemorySize, P_SMEM);

    const long SF = (long)SEQ * FDIM;
    const long SS = (long)SEQ * SEQ;

    // 1) fused split (x + Wq + Wk + Wv)
    {
        int n4x = (NTOT * FDIM) / 4;
        int n4w = (FDIM * FDIM) / 4;
        int total = n4x + 3 * n4w;
        split_all<<<(total + 255) / 256, 256>>>(x, Wq, Wk, Wv,
                                                xh, xl, wh, wl, n4x, n4w);
    }

    // 2) fused projections (q, k bf16 hi/lo; v transposed fp16 hi)
    {
        dim3 grid(FDIM / BN, NTOT / BM, 3);
        proj_kernel<<<grid, NTHR, SMEM_BYTES>>>(xh, xl, wh, wl, bq, bk, bv,
                                                qh, ql, kh, kl, vth);
    }

    // 3) logits = q k^T per batch (bf16 3-term)
    {
        dim3 grid(SEQ / BN, SEQ / BM, BATCH);
        gemm_qk<<<grid, NTHR, SMEM_BYTES>>>(
            (const uint16_t*)qh, (const uint16_t*)ql, SF, FDIM,
            (const uint16_t*)kh, (const uint16_t*)kl, SF, FDIM,
            logits, SS, SEQ, FDIM);
    }

    // 4) softmax -> P fp16
    softmax_f16<<<BATCH * SEQ, 256>>>(logits, ph);

    // 5) out = P v per batch (fp16 1-term, occ-3 PV kernel)
    {
        dim3 grid(FDIM / BN, SEQ / BM, BATCH);
        pv_gemm<<<grid, NTHR, P_SMEM>>>(
            (const uint16_t*)ph, SS,
            (const uint16_t*)vth, (long)FDIM * SEQ,
            out, SF);
    }
}

// round 17
// speedup vs baseline: 1.0182x; 1.0182x over previous
#include <cuda_runtime.h>
#include <cuda_bf16.h>
#include <cuda_fp16.h>
#include <cstdint>

namespace {

constexpr int BATCH = 4;
constexpr int SEQ   = 2048;
constexpr int FDIM  = 1024;
constexpr int NTOT  = BATCH * SEQ;   // 8192

constexpr int NTHR = 128;

// ---- 3-term kernels: 64x128 CTA tile, BK=32 (64B rows, 80B padded), occ 3
constexpr int BM = 64, BN = 128, BK = 32;
constexpr int R3_ROW     = 80;                   // 64B data + 16B pad (conflict-free)
constexpr int A_OP_BYTES = 64  * R3_ROW;         // 5120
constexpr int B_OP_BYTES = 128 * R3_ROW;         // 10240
constexpr int STAGE_BYTES = 2 * A_OP_BYTES + 2 * B_OP_BYTES;   // 30720
constexpr int SMEM_BYTES  = 2 * STAGE_BYTES;     // 61440

// ---- PV kernel (1-term fp16): R14 config — CTA 128x128, 64x64 warps, BK=64
constexpr int PBM = 128, PBN = 128, PBK = 64;
constexpr int P_ROW  = 144;                      // 128B data + 16B pad
constexpr int P_AOP  = 128 * P_ROW;              // 18432
constexpr int P_STAGE = 2 * P_AOP;               // 36864
constexpr int P_SMEM  = 2 * P_STAGE;             // 73728

// ---------------- device scratch ----------------
__device__ __nv_bfloat16 g_xh[(size_t)NTOT * FDIM];
__device__ __nv_bfloat16 g_xl[(size_t)NTOT * FDIM];
__device__ __nv_bfloat16 g_wh[(size_t)3 * FDIM * FDIM];
__device__ __nv_bfloat16 g_wl[(size_t)3 * FDIM * FDIM];
__device__ __nv_bfloat16 g_qh[(size_t)NTOT * FDIM];
__device__ __nv_bfloat16 g_ql[(size_t)NTOT * FDIM];
__device__ __nv_bfloat16 g_kh[(size_t)NTOT * FDIM];
__device__ __nv_bfloat16 g_kl[(size_t)NTOT * FDIM];
__device__ __half        g_vth[(size_t)NTOT * FDIM];  // v^T [b][o][s], fp16 hi only
__device__ float         g_logits[(size_t)BATCH * SEQ * SEQ];
__device__ __half        g_ph[(size_t)BATCH * SEQ * SEQ];   // P fp16 (single)

// ---------------- helpers ----------------
__device__ __forceinline__ uint32_t smem_u32(const void* p) {
    uint32_t a;
    asm("{ .reg .u64 t; cvta.to.shared.u64 t, %1; cvt.u32.u64 %0, t; }"
        : "=r"(a) : "l"(p));
    return a;
}
__device__ __forceinline__ void cp16(uint32_t saddr, const void* gaddr) {
    asm volatile("cp.async.cg.shared.global [%0], [%1], 16;"
                 :: "r"(saddr), "l"(gaddr) : "memory");
}
__device__ __forceinline__ void cp_commit() {
    asm volatile("cp.async.commit_group;" ::: "memory");
}
template<int N>
__device__ __forceinline__ void cp_wait() {
    asm volatile("cp.async.wait_group %0;" :: "n"(N) : "memory");
}

#define LDSM_X4(R, addr) \
    asm volatile("ldmatrix.sync.aligned.m8n8.x4.shared.b16 {%0,%1,%2,%3}, [%4];" \
                 : "=r"((R)[0]), "=r"((R)[1]), "=r"((R)[2]), "=r"((R)[3]) \
                 : "r"(addr))

__device__ __forceinline__ void mma_bf16(float* d, const uint32_t* a,
                                         uint32_t b0, uint32_t b1) {
    asm volatile("mma.sync.aligned.m16n8k16.row.col.f32.bf16.bf16.f32 "
                 "{%0,%1,%2,%3}, {%4,%5,%6,%7}, {%8,%9}, {%0,%1,%2,%3};"
                 : "+f"(d[0]), "+f"(d[1]), "+f"(d[2]), "+f"(d[3])
                 : "r"(a[0]), "r"(a[1]), "r"(a[2]), "r"(a[3]), "r"(b0), "r"(b1));
}
__device__ __forceinline__ void mma_f16(float* d, const uint32_t* a,
                                        uint32_t b0, uint32_t b1) {
    asm volatile("mma.sync.aligned.m16n8k16.row.col.f32.f16.f16.f32 "
                 "{%0,%1,%2,%3}, {%4,%5,%6,%7}, {%8,%9}, {%0,%1,%2,%3};"
                 : "+f"(d[0]), "+f"(d[1]), "+f"(d[2]), "+f"(d[3])
                 : "r"(a[0]), "r"(a[1]), "r"(a[2]), "r"(a[3]), "r"(b0), "r"(b1));
}

__device__ __forceinline__ void split2(float v, __nv_bfloat16& h, __nv_bfloat16& l) {
    h = __float2bfloat16(v);
    l = __float2bfloat16(v - __bfloat162float(h));
}

// ============================================================================
// 3-term mainloop: 4 warps = 2(M) x 2(N); warp tile 32x64; acc[2][8][4].
// AhBh + AhBl + AlBh, fp32 acc. BK=32 (2 k16 steps/chunk), 80B rows.
// ============================================================================
__device__ __forceinline__ void run_mainloop3(
    const uint16_t* __restrict__ Ah, const uint16_t* __restrict__ Al,
    const uint16_t* __restrict__ Bh, const uint16_t* __restrict__ Bl,
    int ldA, int ldB, int K, uint32_t smem_u, int tid,
    float acc[2][8][4])
{
    const int wid = tid >> 5, lid = tid & 31;
    const int warp_m = wid & 1, warp_n = wid >> 1;   // 2 x 2
    const int q = lid >> 3, lr = lid & 7;
    const int rowA = (q & 1) * 8 + lr, kA8 = (q >> 1) * 8;
    const int rowB = (q >> 1) * 8 + lr, kB8 = (q & 1) * 8;

    auto issue = [&](int c) {
        const int k0 = c * BK;
        const uint32_t st = smem_u + (c & 1) * STAGE_BYTES;
#pragma unroll
        for (int op = 0; op < 2; op++) {
            const uint16_t* s = op ? Al : Ah;
#pragma unroll
            for (int i = 0; i < 2; i++) {
                int seg = i * NTHR + tid;
                int r = seg >> 2, cs = seg & 3;
                cp16(st + op * A_OP_BYTES + r * R3_ROW + cs * 16,
                     s + (size_t)r * ldA + k0 + cs * 8);
            }
        }
#pragma unroll
        for (int op = 0; op < 2; op++) {
            const uint16_t* s = op ? Bl : Bh;
#pragma unroll
            for (int i = 0; i < 4; i++) {
                int seg = i * NTHR + tid;
                int r = seg >> 2, cs = seg & 3;
                cp16(st + 2 * A_OP_BYTES + op * B_OP_BYTES + r * R3_ROW + cs * 16,
                     s + (size_t)r * ldB + k0 + cs * 8);
            }
        }
        cp_commit();
    };

    const int NC = K / BK;
    issue(0);

    for (int c = 0; c < NC; c++) {
        if (c + 1 < NC) { issue(c + 1); cp_wait<1>(); }
        else            { cp_wait<0>(); }
        __syncthreads();

        const uint32_t st = smem_u + (c & 1) * STAGE_BYTES;
        const uint32_t aH = st + (warp_m * 32 + rowA) * R3_ROW + kA8 * 2;
        const uint32_t aL = aH + A_OP_BYTES;
        const uint32_t bH = st + 2 * A_OP_BYTES
                          + (warp_n * 64 + rowB) * R3_ROW + kB8 * 2;
        const uint32_t bL = bH + B_OP_BYTES;

#pragma unroll
        for (int ks = 0; ks < 2; ks++) {
            const int kb = ks * 32;
            uint32_t ah[2][4], al[2][4], bh[4][4], bl[4][4];
#pragma unroll
            for (int t = 0; t < 2; t++) {
                LDSM_X4(ah[t], aH + t * 16 * R3_ROW + kb);
                LDSM_X4(al[t], aL + t * 16 * R3_ROW + kb);
            }
#pragma unroll
            for (int p = 0; p < 4; p++) {
                LDSM_X4(bh[p], bH + p * 16 * R3_ROW + kb);
                LDSM_X4(bl[p], bL + p * 16 * R3_ROW + kb);
            }
#pragma unroll
            for (int t = 0; t < 2; t++) {
#pragma unroll
                for (int p = 0; p < 4; p++) {
#pragma unroll
                    for (int h = 0; h < 2; h++) {
                        float* d = acc[t][2 * p + h];
                        mma_bf16(d, ah[t], bh[p][2 * h], bh[p][2 * h + 1]);
                        mma_bf16(d, ah[t], bl[p][2 * h], bl[p][2 * h + 1]);
                        mma_bf16(d, al[t], bh[p][2 * h], bh[p][2 * h + 1]);
                    }
                }
            }
        }
        __syncthreads();
    }
}

// ============================================================================
// QK^T GEMM (bf16 3-term, fp32 epilogue)
// ============================================================================
__global__ __launch_bounds__(NTHR, 3)
void gemm_qk(const uint16_t* __restrict__ Ah, const uint16_t* __restrict__ Al,
             long sA, int ldA,
             const uint16_t* __restrict__ Bh, const uint16_t* __restrict__ Bl,
             long sB, int ldB,
             float* __restrict__ dst, long sC, int ldC, int K)
{
    extern __shared__ char smem[];
    const uint32_t smem_u = smem_u32(smem);
    const int tid = threadIdx.x;
    const int wid = tid >> 5, lid = tid & 31;
    const int warp_m = wid & 1, warp_n = wid >> 1;
    const int m0 = blockIdx.y * BM, n0 = blockIdx.x * BN;

    const uint16_t* ah = Ah + (long)blockIdx.z * sA + (size_t)m0 * ldA;
    const uint16_t* al = Al + (long)blockIdx.z * sA + (size_t)m0 * ldA;
    const uint16_t* bh = Bh + (long)blockIdx.z * sB + (size_t)n0 * ldB;
    const uint16_t* bl = Bl + (long)blockIdx.z * sB + (size_t)n0 * ldB;

    float acc[2][8][4];
#pragma unroll
    for (int t = 0; t < 2; t++)
#pragma unroll
        for (int n = 0; n < 8; n++)
#pragma unroll
            for (int e = 0; e < 4; e++) acc[t][n][e] = 0.0f;

    run_mainloop3(ah, al, bh, bl, ldA, ldB, K, smem_u, tid, acc);

    const int tq = lid >> 2, tr2 = (lid & 3) * 2;
    float* base = dst + (long)blockIdx.z * sC;
#pragma unroll
    for (int t = 0; t < 2; t++) {
        long m = m0 + warp_m * 32 + t * 16 + tq;
#pragma unroll
        for (int j = 0; j < 8; j++) {
            int n = n0 + warp_n * 64 + j * 8 + tr2;
            *reinterpret_cast<float2*>(base + m * ldC + n) =
                make_float2(acc[t][j][0], acc[t][j][1]);
            *reinterpret_cast<float2*>(base + (m + 8) * ldC + n) =
                make_float2(acc[t][j][2], acc[t][j][3]);
        }
    }
}

// ============================================================================
// PV GEMM (R14 config): fp16 1-term, CTA 128x128, 4 warps of 64x64, BK=64.
// out[m,n] = sum_k P[m,k] * Vt[n,k]
// ============================================================================
__global__ __launch_bounds__(NTHR, 2)
void pv_gemm(const uint16_t* __restrict__ P, long sP,
             const uint16_t* __restrict__ Vt, long sV,
             float* __restrict__ dst, long sC)
{
    extern __shared__ char smem[];
    const uint32_t smem_u = smem_u32(smem);
    const int tid = threadIdx.x;
    const int wid = tid >> 5, lid = tid & 31;
    const int warp_m = wid & 1, warp_n = wid >> 1;   // 2 x 2 of 64x64
    const int m0 = blockIdx.y * PBM, n0 = blockIdx.x * PBN;
    const int ldA = SEQ, ldB = SEQ, K = SEQ;

    const uint16_t* ah = P  + (long)blockIdx.z * sP + (size_t)m0 * ldA;
    const uint16_t* bh = Vt + (long)blockIdx.z * sV + (size_t)n0 * ldB;

    const int q = lid >> 3, lr = lid & 7;
    const int rowA = (q & 1) * 8 + lr, kA8 = (q >> 1) * 8;
    const int rowB = (q >> 1) * 8 + lr, kB8 = (q & 1) * 8;

    float acc[4][8][4];
#pragma unroll
    for (int t = 0; t < 4; t++)
#pragma unroll
        for (int n = 0; n < 8; n++)
#pragma unroll
            for (int e = 0; e < 4; e++) acc[t][n][e] = 0.0f;

    auto issue = [&](int c) {
        const int k0 = c * PBK;
        const uint32_t st = smem_u + (c & 1) * P_STAGE;
#pragma unroll
        for (int i = 0; i < 8; i++) {
            int seg = i * NTHR + tid;
            int r = seg >> 3, cs = seg & 7;
            cp16(st + r * P_ROW + cs * 16, ah + (size_t)r * ldA + k0 + cs * 8);
        }
#pragma unroll
        for (int i = 0; i < 8; i++) {
            int seg = i * NTHR + tid;
            int r = seg >> 3, cs = seg & 7;
            cp16(st + P_AOP + r * P_ROW + cs * 16,
                 bh + (size_t)r * ldB + k0 + cs * 8);
        }
        cp_commit();
    };

    const int NC = K / PBK;
    issue(0);

    for (int c = 0; c < NC; c++) {
        if (c + 1 < NC) { issue(c + 1); cp_wait<1>(); }
        else            { cp_wait<0>(); }
        __syncthreads();

        const uint32_t st = smem_u + (c & 1) * P_STAGE;
        const uint32_t aH = st + (warp_m * 64 + rowA) * P_ROW + kA8 * 2;
        const uint32_t bH = st + P_AOP + (warp_n * 64 + rowB) * P_ROW + kB8 * 2;

#pragma unroll
        for (int ks = 0; ks < 4; ks++) {
            const int kb = ks * 32;
            uint32_t af[4][4];
#pragma unroll
            for (int t = 0; t < 4; t++)
                LDSM_X4(af[t], aH + t * 16 * P_ROW + kb);
#pragma unroll
            for (int p = 0; p < 4; p++) {
                uint32_t bf[4];
                LDSM_X4(bf, bH + p * 16 * P_ROW + kb);
#pragma unroll
                for (int t = 0; t < 4; t++) {
#pragma unroll
                    for (int h = 0; h < 2; h++)
                        mma_f16(acc[t][2 * p + h], af[t], bf[2 * h], bf[2 * h + 1]);
                }
            }
        }
        __syncthreads();
    }

    const int tq = lid >> 2, tr2 = (lid & 3) * 2;
    float* base = dst + (long)blockIdx.z * sC;
#pragma unroll
    for (int t = 0; t < 4; t++) {
        long m = m0 + warp_m * 64 + t * 16 + tq;
#pragma unroll
        for (int j = 0; j < 8; j++) {
            int n = n0 + warp_n * 64 + j * 8 + tr2;
            *reinterpret_cast<float2*>(base + m * FDIM + n) =
                make_float2(acc[t][j][0], acc[t][j][1]);
            *reinterpret_cast<float2*>(base + (m + 8) * FDIM + n) =
                make_float2(acc[t][j][2], acc[t][j][3]);
        }
    }
}

// ============================================================================
// Fused projection kernel: z=0 -> q (bf16 hi/lo), z=1 -> k (bf16 hi/lo),
// z=2 -> v transposed (fp16 hi only). relu(x W^T + b). bf16 3-term mainloop.
// ============================================================================
__global__ __launch_bounds__(NTHR, 3)
void proj_kernel(const __nv_bfloat16* __restrict__ xh, const __nv_bfloat16* __restrict__ xl,
                 const __nv_bfloat16* __restrict__ wh, const __nv_bfloat16* __restrict__ wl,
                 const float* __restrict__ bq, const float* __restrict__ bk,
                 const float* __restrict__ bv,
                 __nv_bfloat16* __restrict__ qh, __nv_bfloat16* __restrict__ ql,
                 __nv_bfloat16* __restrict__ kh, __nv_bfloat16* __restrict__ kl,
                 __half* __restrict__ vth)
{
    extern __shared__ char smem[];
    const uint32_t smem_u = smem_u32(smem);
    const int tid = threadIdx.x;
    const int wid = tid >> 5, lid = tid & 31;
    const int warp_m = wid & 1, warp_n = wid >> 1;
    const int m0 = blockIdx.y * BM, n0 = blockIdx.x * BN;
    const int z = blockIdx.z;
    const long WSZ = (long)FDIM * FDIM;

    const float* bias = (z == 0) ? bq : (z == 1) ? bk : bv;
    const uint16_t* ah = (const uint16_t*)xh + (size_t)m0 * FDIM;
    const uint16_t* al = (const uint16_t*)xl + (size_t)m0 * FDIM;
    const uint16_t* bhp = (const uint16_t*)wh + z * WSZ + (size_t)n0 * FDIM;
    const uint16_t* blp = (const uint16_t*)wl + z * WSZ + (size_t)n0 * FDIM;

    float acc[2][8][4];
#pragma unroll
    for (int t = 0; t < 2; t++)
#pragma unroll
        for (int n = 0; n < 8; n++)
#pragma unroll
            for (int e = 0; e < 4; e++) acc[t][n][e] = 0.0f;

    run_mainloop3(ah, al, bhp, blp, FDIM, FDIM, FDIM, smem_u, tid, acc);

    const int tq = lid >> 2, tr2 = (lid & 3) * 2;

    if (z < 2) {
        __nv_bfloat16* dh = (z == 0) ? qh : kh;
        __nv_bfloat16* dl = (z == 0) ? ql : kl;
#pragma unroll
        for (int t = 0; t < 2; t++) {
            long m = m0 + warp_m * 32 + t * 16 + tq;
#pragma unroll
            for (int j = 0; j < 8; j++) {
                int n = n0 + warp_n * 64 + j * 8 + tr2;
                float b0 = bias[n], b1 = bias[n + 1];
#pragma unroll
                for (int h = 0; h < 2; h++) {
                    float v0 = fmaxf(acc[t][j][2 * h + 0] + b0, 0.0f);
                    float v1 = fmaxf(acc[t][j][2 * h + 1] + b1, 0.0f);
                    __nv_bfloat16 h0, l0, h1, l1;
                    split2(v0, h0, l0); split2(v1, h1, l1);
                    long row = m + 8 * h;
                    *reinterpret_cast<__nv_bfloat162*>(dh + row * FDIM + n) =
                        __nv_bfloat162(h0, h1);
                    *reinterpret_cast<__nv_bfloat162*>(dl + row * FDIM + n) =
                        __nv_bfloat162(l0, l1);
                }
            }
        }
    } else {
        // v: relu+bias, stage fp32 in smem [64][129], write transposed fp16
        float* smf = (float*)smem;
#pragma unroll
        for (int t = 0; t < 2; t++) {
            int ml = warp_m * 32 + t * 16 + tq;
#pragma unroll
            for (int j = 0; j < 8; j++) {
                int nl = warp_n * 64 + j * 8 + tr2;
                float b0 = bias[n0 + nl], b1 = bias[n0 + nl + 1];
                smf[ml * 129 + nl]           = fmaxf(acc[t][j][0] + b0, 0.0f);
                smf[ml * 129 + nl + 1]       = fmaxf(acc[t][j][1] + b1, 0.0f);
                smf[(ml + 8) * 129 + nl]     = fmaxf(acc[t][j][2] + b0, 0.0f);
                smf[(ml + 8) * 129 + nl + 1] = fmaxf(acc[t][j][3] + b1, 0.0f);
            }
        }
        __syncthreads();
        const int o_l = tid;                 // 0..127 output feature
        const long bidx = m0 >> 11;
        const long s_g  = (m0 & 2047);
        __half* dh = vth + bidx * (long)FDIM * SEQ
                     + (long)(n0 + o_l) * SEQ + s_g;
#pragma unroll
        for (int g = 0; g < 64; g += 8) {
            __align__(16) __half hb[8];
#pragma unroll
            for (int j = 0; j < 8; j++)
                hb[j] = __float2half(smf[(g + j) * 129 + o_l]);
            *reinterpret_cast<uint4*>(dh + g) = *reinterpret_cast<const uint4*>(hb);
        }
    }
}

// ---------------- fused split: x, Wq, Wk, Wv -> bf16 hi/lo ----------------
__global__ __launch_bounds__(256)
void split_all(const float* __restrict__ x,
               const float* __restrict__ wq, const float* __restrict__ wk,
               const float* __restrict__ wv,
               __nv_bfloat16* __restrict__ xh, __nv_bfloat16* __restrict__ xl,
               __nv_bfloat16* __restrict__ wh, __nv_bfloat16* __restrict__ wl,
               int n4x, int n4w)
{
    int i = blockIdx.x * blockDim.x + threadIdx.x;
    const float* src; __nv_bfloat16 *dh, *dl; int idx;
    if (i < n4x)                { src = x;  dh = xh; dl = xl; idx = i; }
    else if (i < n4x + n4w)     { src = wq; dh = wh; dl = wl; idx = i - n4x; }
    else if (i < n4x + 2*n4w)   { src = wk; dh = wh + (long)FDIM*FDIM;
                                  dl = wl + (long)FDIM*FDIM; idx = i - n4x - n4w; }
    else if (i < n4x + 3*n4w)   { src = wv; dh = wh + 2L*FDIM*FDIM;
                                  dl = wl + 2L*FDIM*FDIM; idx = i - n4x - 2*n4w; }
    else return;

    float4 v = reinterpret_cast<const float4*>(src)[idx];
    __align__(8) __nv_bfloat16 hb[4], lb[4];
    split2(v.x, hb[0], lb[0]); split2(v.y, hb[1], lb[1]);
    split2(v.z, hb[2], lb[2]); split2(v.w, hb[3], lb[3]);
    reinterpret_cast<uint2*>(dh)[idx] = *reinterpret_cast<const uint2*>(hb);
    reinterpret_cast<uint2*>(dl)[idx] = *reinterpret_cast<const uint2*>(lb);
}

// ---------------- softmax row 2048, fp16 out; shfl reductions ----------------
__global__ __launch_bounds__(256)
void softmax_f16(const float* __restrict__ L, __half* __restrict__ ph)
{
    const int tid = threadIdx.x;
    const int wid = tid >> 5, lid = tid & 31;
    const float* row = L + (size_t)blockIdx.x * SEQ;

    float4 v0 = reinterpret_cast<const float4*>(row)[tid];
    float4 v1 = reinterpret_cast<const float4*>(row)[tid + 256];

    float mx = fmaxf(fmaxf(fmaxf(v0.x, v0.y), fmaxf(v0.z, v0.w)),
                     fmaxf(fmaxf(v1.x, v1.y), fmaxf(v1.z, v1.w)));
#pragma unroll
    for (int s = 16; s > 0; s >>= 1)
        mx = fmaxf(mx, __shfl_xor_sync(0xFFFFFFFFu, mx, s));

    __shared__ float red[8];
    if (lid == 0) red[wid] = mx;
    __syncthreads();
    {
        float m = red[lid & 7];
#pragma unroll
        for (int s = 4; s > 0; s >>= 1)
            m = fmaxf(m, __shfl_xor_sync(0xFFFFFFFFu, m, s));
        mx = m;
    }

    float e0x = __expf(v0.x - mx), e0y = __expf(v0.y - mx);
    float e0z = __expf(v0.z - mx), e0w = __expf(v0.w - mx);
    float e1x = __expf(v1.x - mx), e1y = __expf(v1.y - mx);
    float e1z = __expf(v1.z - mx), e1w = __expf(v1.w - mx);

    float sum = (e0x + e0y + e0z + e0w) + (e1x + e1y + e1z + e1w);
#pragma unroll
    for (int s = 16; s > 0; s >>= 1)
        sum += __shfl_xor_sync(0xFFFFFFFFu, sum, s);

    __shared__ float red2[8];
    if (lid == 0) red2[wid] = sum;
    __syncthreads();
    {
        float s8 = red2[lid & 7];
#pragma unroll
        for (int s = 4; s > 0; s >>= 1)
            s8 += __shfl_xor_sync(0xFFFFFFFFu, s8, s);
        sum = s8;
    }
    float inv = 1.0f / sum;

    __half* ph_row = ph + (size_t)blockIdx.x * SEQ;
    __align__(8) __half hb[4];

    hb[0] = __float2half(e0x * inv); hb[1] = __float2half(e0y * inv);
    hb[2] = __float2half(e0z * inv); hb[3] = __float2half(e0w * inv);
    reinterpret_cast<uint2*>(ph_row)[tid] = *reinterpret_cast<const uint2*>(hb);

    hb[0] = __float2half(e1x * inv); hb[1] = __float2half(e1y * inv);
    hb[2] = __float2half(e1z * inv); hb[3] = __float2half(e1w * inv);
    reinterpret_cast<uint2*>(ph_row)[tid + 256] = *reinterpret_cast<const uint2*>(hb);
}

} // namespace

extern "C" void kernel_launch(void* const* d_in, const int* in_sizes, int n_in,
                              void* d_out, int out_size)
{
    const float* x  = (const float*)d_in[0];
    const float* Wq = (const float*)d_in[1];
    const float* bq = (const float*)d_in[2];
    const float* Wk = (const float*)d_in[3];
    const float* bk = (const float*)d_in[4];
    const float* Wv = (const float*)d_in[5];
    const float* bv = (const float*)d_in[6];
    float* out = (float*)d_out;

    __nv_bfloat16 *xh, *xl, *wh, *wl, *qh, *ql, *kh, *kl;
    __half *vth, *ph;
    float* logits;
    cudaGetSymbolAddress((void**)&xh, g_xh);   cudaGetSymbolAddress((void**)&xl, g_xl);
    cudaGetSymbolAddress((void**)&wh, g_wh);   cudaGetSymbolAddress((void**)&wl, g_wl);
    cudaGetSymbolAddress((void**)&qh, g_qh);   cudaGetSymbolAddress((void**)&ql, g_ql);
    cudaGetSymbolAddress((void**)&kh, g_kh);   cudaGetSymbolAddress((void**)&kl, g_kl);
    cudaGetSymbolAddress((void**)&vth, g_vth);
    cudaGetSymbolAddress((void**)&ph, g_ph);
    cudaGetSymbolAddress((void**)&logits, g_logits);

    cudaFuncSetAttribute(proj_kernel,
                         cudaFuncAttributeMaxDynamicSharedMemorySize, SMEM_BYTES);
    cudaFuncSetAttribute(gemm_qk,
                         cudaFuncAttributeMaxDynamicSharedMemorySize, SMEM_BYTES);
    cudaFuncSetAttribute(pv_gemm,
                         cudaFuncAttributeMaxDynamicSharedMemorySize, P_SMEM);

    const long SF = (long)SEQ * FDIM;
    const long SS = (long)SEQ * SEQ;

    // 1) fused split (x + Wq + Wk + Wv)
    {
        int n4x = (NTOT * FDIM) / 4;
        int n4w = (FDIM * FDIM) / 4;
        int total = n4x + 3 * n4w;
        split_all<<<(total + 255) / 256, 256>>>(x, Wq, Wk, Wv,
                                                xh, xl, wh, wl, n4x, n4w);
    }

    // 2) fused projections (q, k bf16 hi/lo; v transposed fp16 hi)
    {
        dim3 grid(FDIM / BN, NTOT / BM, 3);
        proj_kernel<<<grid, NTHR, SMEM_BYTES>>>(xh, xl, wh, wl, bq, bk, bv,
                                                qh, ql, kh, kl, vth);
    }

    // 3) logits = q k^T per batch (bf16 3-term)
    {
        dim3 grid(SEQ / BN, SEQ / BM, BATCH);
        gemm_qk<<<grid, NTHR, SMEM_BYTES>>>(
            (const uint16_t*)qh, (const uint16_t*)ql, SF, FDIM,
            (const uint16_t*)kh, (const uint16_t*)kl, SF, FDIM,
            logits, SS, SEQ, FDIM);
    }

    // 4) softmax -> P fp16 (shfl reductions)
    softmax_f16<<<BATCH * SEQ, 256>>>(logits, ph);

    // 5) out = P v per batch (fp16 1-term, R14 PV kernel)
    {
        dim3 grid(FDIM / PBN, SEQ / PBM, BATCH);
        pv_gemm<<<grid, NTHR, P_SMEM>>>(
            (const uint16_t*)ph, SS,
            (const uint16_t*)vth, (long)FDIM * SEQ,
            out, SF);
    }
}